// round 5
// baseline (speedup 1.0000x reference)
#include <cuda_runtime.h>

#define NB 16
#define NA 3
#define NM 32
#define NC 80
#define NH 80
#define NW 80
#define NHW (NH * NW)                 // 6400
#define CH (NA * (5 + NC) + NA * NM)  // 351
#define NE (NB * NA * NHW)            // 307200
#define TPB 256
#define NBLK (NE / TPB)               // 1200
#define THRESH 0.05f
#define STRIDEF 8.0f
#define ROW (7 + NM)                  // 39

// state word: bits[63:62]=flag (0=invalid,1=AGG,2=PRE), bit[61]=round parity,
// bits[31:0]=count. Round parity makes stale entries from the previous launch
// read as invalid, so no reset kernel is needed.
__device__ unsigned long long g_state[NBLK];   // zero-init at load
__device__ int g_done  = 0;
__device__ int g_round = 0;

__global__ void __launch_bounds__(TPB, 6)
fused_kernel(const float* __restrict__ in, const float* __restrict__ anchors,
             float* __restrict__ out, long long out_size)
{
    const int tid  = threadIdx.x;
    const int lane = tid & 31;
    const int wid  = tid >> 5;
    const int bid  = blockIdx.x;

    const int round = g_round;
    const unsigned long long RB = (unsigned long long)round << 61;

    const int e = bid * TPB + tid;
    const int b = e / (NA * NHW);
    const int r = e - b * (NA * NHW);
    const int a = r / NHW;
    const int p = r - a * NHW;

    const float* base = in + ((size_t)b * CH + (size_t)a * (5 + NC)) * NHW + p;

    // hoist objectness load (overlaps class loop latency)
    const float oraw = __ldg(base + 4 * NHW);

    // ---- max-free softmax: 4 split sums, batches of 16 independent loads ----
    float s0 = 0.f, s1 = 0.f, s2 = 0.f, s3 = 0.f;
    float m = -1e30f;
    int idx = 0;
    const float* cb = base + 5 * NHW;
#pragma unroll 4
    for (int c = 0; c < NC; c += 4) {
        float xa = __ldg(cb + (c + 0) * NHW);
        float xb = __ldg(cb + (c + 1) * NHW);
        float xc = __ldg(cb + (c + 2) * NHW);
        float xd = __ldg(cb + (c + 3) * NHW);
        s0 += __expf(xa); if (xa > m) { m = xa; idx = c; }
        s1 += __expf(xb); if (xb > m) { m = xb; idx = c + 1; }
        s2 += __expf(xc); if (xc > m) { m = xc; idx = c + 2; }
        s3 += __expf(xd); if (xd > m) { m = xd; idx = c + 3; }
    }
    const float s = (s0 + s1) + (s2 + s3);

    const float obj = 1.0f / (1.0f + expf(-oraw));   // accurate: threshold-critical
    const float score = obj * __expf(m) / s;
    const bool keep = score > THRESH;

    // ---- block rank + decoupled lookback (2 barriers total) ----
    __shared__ int s_warp[TPB / 32];
    __shared__ int s_base;
    const unsigned ball = __ballot_sync(0xffffffffu, keep);
    if (lane == 0) s_warp[wid] = __popc(ball);
    __syncthreads();

    if (wid == 0) {
        // cross-warp inclusive prefix in registers (8 warps)
        int w = (lane < TPB / 32) ? s_warp[lane] : 0;
#pragma unroll
        for (int d = 1; d < TPB / 32; d <<= 1) {
            int n = __shfl_up_sync(0xffffffffu, w, d);
            if (lane >= d) w += n;
        }
        if (lane < TPB / 32) s_warp[lane] = w;
        const int total = __shfl_sync(0xffffffffu, w, TPB / 32 - 1);

        if (bid == 0) {
            if (lane == 0) {
                atomicExch(&g_state[0], (2ull << 62) | RB | (unsigned)total);
                s_base = 0;
            }
        } else {
            if (lane == 0)
                atomicExch(&g_state[bid], (1ull << 62) | RB | (unsigned)total);
            int excl = 0;
            int j = bid - 1;
            while (j >= 0) {
                const int gidx = j - lane;
                const bool valid = gidx >= 0;
                unsigned long long v;
                bool ready;
                do {
                    v = valid ? atomicAdd(&g_state[gidx], 0ull)
                              : ((2ull << 62) | RB);
                    ready = ((v >> 62) != 0ull) && (((v >> 61) & 1ull) == (unsigned long long)round);
                } while (__any_sync(0xffffffffu, !ready));
                const unsigned pmask = __ballot_sync(0xffffffffu, (v >> 62) == 2ull);
                const int cut = pmask ? (__ffs(pmask) - 1) : 32;
                const unsigned add = (lane <= (cut < 31 ? cut : 31)) ? (unsigned)(v & 0xffffffffu) : 0u;
                excl += (int)__reduce_add_sync(0xffffffffu, add);
                if (cut < 32) break;
                j -= 32;
            }
            if (lane == 0) {
                atomicExch(&g_state[bid], (2ull << 62) | RB | (unsigned)(excl + total));
                s_base = excl;
            }
        }
    }
    __syncthreads();

    // launch-parity bookkeeping: last block to finish flips the round
    if (tid == 0) {
        const int d = atomicAdd(&g_done, 1);
        if (d == NBLK - 1) { g_done = 0; g_round = round ^ 1; }
    }

    const int total = s_warp[TPB / 32 - 1];
    if (total == 0) return;

    const int texcl = (wid ? s_warp[wid - 1] : 0) + __popc(ball & ((1u << lane) - 1u));
    const int row = s_base + texcl;
    const long long o = (long long)row * ROW;
    const bool wok = keep && (o + ROW <= out_size);

    if (wok) {
        const float x0 = __ldg(base + 0 * NHW);
        const float y0 = __ldg(base + 1 * NHW);
        const float w0 = __ldg(base + 2 * NHW);
        const float h0 = __ldg(base + 3 * NHW);

        const float aw = anchors[a * 2 + 0];
        const float ah = anchors[a * 2 + 1];
        const float amax = fmaxf(fmaxf(fmaxf(anchors[0], anchors[1]),
                                       fmaxf(anchors[2], anchors[3])),
                                 fmaxf(anchors[4], anchors[5]));
        const float maxv = floorf(logf(1e35f / amax / STRIDEF));

        const float xs = (1.0f / (1.0f + __expf(-x0)) + (float)(p % NW)) * STRIDEF;
        const float ys = (1.0f / (1.0f + __expf(-y0)) + (float)(p / NW)) * STRIDEF;
        const float wv = __expf(fminf(w0, maxv)) * aw * STRIDEF;
        const float hv = __expf(fminf(h0, maxv)) * ah * STRIDEF;

        out[o + 0] = (float)b;
        out[o + 1] = xs;
        out[o + 2] = ys;
        out[o + 3] = wv;
        out[o + 4] = hv;
        out[o + 5 + NM] = score;
        out[o + 6 + NM] = (float)idx;

        const float* mb = in + ((size_t)b * CH + NA * (5 + NC) + (size_t)a * NM) * NHW + p;
#pragma unroll 8
        for (int mi = 0; mi < NM; ++mi)
            out[o + 5 + mi] = __ldg(mb + mi * NHW);
    }
}

extern "C" void kernel_launch(void* const* d_in, const int* in_sizes, int n_in,
                              void* d_out, int out_size)
{
    const float* in      = (const float*)d_in[0];
    const float* anchors = (const float*)d_in[1];
    float* out = (float*)d_out;

    fused_kernel<<<NBLK, TPB>>>(in, anchors, out, (long long)out_size);
}